// round 3
// baseline (speedup 1.0000x reference)
#include <cuda_runtime.h>
#include <math.h>

// ---------------- static scratch (no allocation allowed) ----------------
#define N_MAX 150016
#define E_MAX 900032

__device__ float g_y[(size_t)N_MAX * 256];   // GEMM output (pre-BN), per layer
__device__ float g_z[(size_t)N_MAX * 96];    // aggregated input features
__device__ float g_x[(size_t)N_MAX * 128];   // fc0 output
__device__ int   g_deg[N_MAX];
__device__ int   g_cursor[N_MAX];
__device__ int   g_rowptr[N_MAX + 1];
__device__ int   g_csr_src[E_MAX];
__device__ float g_csr_w[E_MAX];
__device__ float g_dinv[N_MAX];
__device__ float g_cs[N_MAX];
__device__ int   g_blocksum[256];
__device__ int   g_blockoff[256];
__device__ float g_sum[256];
__device__ float g_sq[256];
__device__ float g_scale[256];
__device__ float g_shift[256];
__device__ float g_pool[64 * 128];
__device__ int   g_starts[65];

// ---------------- prep kernels ----------------
__global__ void k_zero(int n) {
    int i = blockIdx.x * blockDim.x + threadIdx.x;
    if (i < n) { g_deg[i] = 0; g_cursor[i] = 0; }
    if (i < 256) { g_sum[i] = 0.f; g_sq[i] = 0.f; }
}

__global__ void k_hist(const int* __restrict__ dst, int e) {
    int i = blockIdx.x * blockDim.x + threadIdx.x;
    if (i < e) atomicAdd(&g_deg[dst[i]], 1);
}

__global__ void k_dinv(int n) {
    int i = blockIdx.x * blockDim.x + threadIdx.x;
    if (i < n) {
        float d = (float)(g_deg[i] + 1);
        float r = rsqrtf(d);
        g_dinv[i] = r;
        g_cs[i] = r * r;
    }
}

__global__ void k_scan1(int n) {
    __shared__ int sh[1024];
    int t = threadIdx.x;
    int idx = blockIdx.x * 1024 + t;
    int v = (idx < n) ? g_deg[idx] : 0;
    sh[t] = v;
    __syncthreads();
    for (int off = 1; off < 1024; off <<= 1) {
        int add = (t >= off) ? sh[t - off] : 0;
        __syncthreads();
        sh[t] += add;
        __syncthreads();
    }
    if (idx < n) g_rowptr[idx] = sh[t] - v;
    if (t == 1023) g_blocksum[blockIdx.x] = sh[t];
}

__global__ void k_scan2(int nb, int n) {
    if (threadIdx.x == 0) {
        int run = 0;
        for (int i = 0; i < nb; i++) { g_blockoff[i] = run; run += g_blocksum[i]; }
        g_rowptr[n] = run;
    }
}

__global__ void k_scan3(int n) {
    int idx = blockIdx.x * 1024 + threadIdx.x;
    if (idx < n) g_rowptr[idx] += g_blockoff[idx >> 10];
}

__global__ void k_place(const int* __restrict__ src, const int* __restrict__ dst, int e) {
    int i = blockIdx.x * blockDim.x + threadIdx.x;
    if (i < e) {
        int d = dst[i], s = src[i];
        int p = g_rowptr[d] + atomicAdd(&g_cursor[d], 1);
        g_csr_src[p] = s;
        g_csr_w[p] = g_dinv[s] * g_dinv[d];
    }
}

// ---------------- aggregation (fused BN+ReLU on input) ----------------
// MODE 0: input = xext (raw pos). MODE 1: input = relu(bn(g_y)) via g_scale/g_shift.
// Warp per node; lanes = channels (up to 96). Edge meta loaded cooperatively.
template<int MODE>
__global__ void k_agg(const float* __restrict__ xext, int n, int din) {
    const float* __restrict__ x = (MODE == 0) ? xext : g_y;
    int gt = blockIdx.x * blockDim.x + threadIdx.x;
    int node = gt >> 5;
    int lane = gt & 31;
    if (node >= n) return;
    int c0 = lane, c1 = lane + 32, c2 = lane + 64;
    bool v0 = c0 < din, v1 = c1 < din, v2 = c2 < din;
    float s0 = 1.f, h0 = 0.f, s1 = 1.f, h1 = 0.f, s2 = 1.f, h2 = 0.f;
    if (MODE) {
        if (v0) { s0 = g_scale[c0]; h0 = g_shift[c0]; }
        if (v1) { s1 = g_scale[c1]; h1 = g_shift[c1]; }
        if (v2) { s2 = g_scale[c2]; h2 = g_shift[c2]; }
    }
    int beg = g_rowptr[node], end = g_rowptr[node + 1];
    float a0 = 0.f, a1 = 0.f, a2 = 0.f;
    for (int base = beg; base < end; base += 32) {
        int p = base + lane;
        int eSrc = 0; float eW = 0.f;
        if (p < end) { eSrc = g_csr_src[p]; eW = g_csr_w[p]; }
        int cnt = min(32, end - base);
        for (int t = 0; t < cnt; t++) {
            int s = __shfl_sync(0xffffffffu, eSrc, t);
            float w = __shfl_sync(0xffffffffu, eW, t);
            const float* xs = x + (size_t)s * din;
            if (v0) { float v = xs[c0]; if (MODE) v = fmaxf(fmaf(v, s0, h0), 0.f); a0 = fmaf(v, w, a0); }
            if (v1) { float v = xs[c1]; if (MODE) v = fmaxf(fmaf(v, s1, h1), 0.f); a1 = fmaf(v, w, a1); }
            if (v2) { float v = xs[c2]; if (MODE) v = fmaxf(fmaf(v, s2, h2), 0.f); a2 = fmaf(v, w, a2); }
        }
    }
    float cw = g_cs[node];
    const float* xi = x + (size_t)node * din;
    float* zi = g_z + (size_t)node * din;
    if (v0) { float v = xi[c0]; if (MODE) v = fmaxf(fmaf(v, s0, h0), 0.f); zi[c0] = fmaf(v, cw, a0); }
    if (v1) { float v = xi[c1]; if (MODE) v = fmaxf(fmaf(v, s1, h1), 0.f); zi[c1] = fmaf(v, cw, a1); }
    if (v2) { float v = xi[c2]; if (MODE) v = fmaxf(fmaf(v, s2, h2), 0.f); zi[c2] = fmaf(v, cw, a2); }
}

// ---------------- small GEMM (K<=16, NC<=32): thread per row, fused stats ----
template<int K, int NC>
__global__ __launch_bounds__(256) void k_gemm_s(
    const float* __restrict__ Bm, const float* __restrict__ bias, int M)
{
    __shared__ float Ws[K * NC];
    __shared__ float bs[NC];
    int tid = threadIdx.x;
    for (int i = tid; i < K * NC; i += 256) Ws[i] = Bm[i];
    if (tid < NC) bs[tid] = bias[tid];
    __syncthreads();

    int r = blockIdx.x * 256 + tid;
    bool valid = r < M;
    float a[K];
    #pragma unroll
    for (int k = 0; k < K; k++) a[k] = valid ? g_z[(size_t)r * K + k] : 0.f;
    float acc[NC];
    #pragma unroll
    for (int c = 0; c < NC; c++) acc[c] = valid ? bs[c] : 0.f;
    #pragma unroll
    for (int k = 0; k < K; k++)
        #pragma unroll
        for (int c = 0; c < NC; c++) acc[c] = fmaf(a[k], Ws[k * NC + c], acc[c]);

    if (valid) {
        float4* dst = (float4*)(g_y + (size_t)r * NC);
        #pragma unroll
        for (int c = 0; c < NC; c += 4)
            dst[c >> 2] = make_float4(acc[c], acc[c + 1], acc[c + 2], acc[c + 3]);
    }
    // fused BN stats (invalid rows contribute 0)
    float q[NC];
    #pragma unroll
    for (int c = 0; c < NC; c++) q[c] = acc[c] * acc[c];
    #pragma unroll
    for (int off = 16; off; off >>= 1) {
        #pragma unroll
        for (int c = 0; c < NC; c++) {
            acc[c] += __shfl_down_sync(0xffffffffu, acc[c], off);
            q[c]   += __shfl_down_sync(0xffffffffu, q[c], off);
        }
    }
    if ((tid & 31) == 0) {
        #pragma unroll
        for (int c = 0; c < NC; c++) {
            atomicAdd(&g_sum[c], acc[c]);
            atomicAdd(&g_sq[c], q[c]);
        }
    }
}

// ---------------- tiled GEMM 128 x (16*TN), BK=8, 8xTN per thread ----------
// FC0==0: C=g_y = g_z @ W + b, fused stats.
// FC0==1: C=g_x = relu( relu(bn(g_y)) @ W + b ), no stats.
template<int TN, int FC0>
__global__ __launch_bounds__(256, 2) void k_gemm_t(
    const float* __restrict__ Bm, const float* __restrict__ bias,
    int M, int K, int Nc)
{
    constexpr int BN = 16 * TN;
    constexpr int NB = (8 * BN + 255) / 256;
    const float* __restrict__ A = FC0 ? g_y : g_z;
    float* __restrict__ C = FC0 ? g_x : g_y;

    __shared__ float As[8][132];      // padded: conflict-free STS
    __shared__ float Bs[8][BN];
    __shared__ float red[16][BN];
    __shared__ float sbn_s[256], sbn_h[256];

    int tid = threadIdx.x;
    int tx = tid & 15, ty = tid >> 4;
    int row0 = blockIdx.y * 128, col0 = blockIdx.x * BN;

    if (FC0) {
        for (int i = tid; i < K; i += 256) { sbn_s[i] = g_scale[i]; sbn_h[i] = g_shift[i]; }
        __syncthreads();
    }

    float acc[8][TN];
    #pragma unroll
    for (int i = 0; i < 8; i++)
        #pragma unroll
        for (int j = 0; j < TN; j++) acc[i][j] = 0.f;

    int ak = tid & 7, ar = tid >> 3;     // A tile coords
    float pa[4], pb[NB];

    auto loadA = [&](int k0) {
        #pragma unroll
        for (int j = 0; j < 4; j++) {
            int row = row0 + ar + j * 32, gk = k0 + ak;
            float v = 0.f;
            if (row < M && gk < K) {
                v = A[(size_t)row * K + gk];
                if (FC0) v = fmaxf(fmaf(v, sbn_s[gk], sbn_h[gk]), 0.f);
            }
            pa[j] = v;
        }
    };
    auto loadB = [&](int k0) {
        #pragma unroll
        for (int j = 0; j < NB; j++) {
            int idx = tid + j * 256;
            if (idx < 8 * BN) {
                int kk = idx / BN, nn = idx % BN;
                int gk = k0 + kk, c = col0 + nn;
                pb[j] = (gk < K && c < Nc) ? Bm[(size_t)gk * Nc + c] : 0.f;
            }
        }
    };
    auto sts = [&]() {
        #pragma unroll
        for (int j = 0; j < 4; j++) As[ak][ar + j * 32] = pa[j];
        #pragma unroll
        for (int j = 0; j < NB; j++) {
            int idx = tid + j * 256;
            if (idx < 8 * BN) Bs[idx / BN][idx % BN] = pb[j];
        }
    };

    loadA(0); loadB(0);
    sts();
    __syncthreads();
    for (int k0 = 8; ; k0 += 8) {
        bool has = k0 < K;
        if (has) { loadA(k0); loadB(k0); }
        #pragma unroll
        for (int k = 0; k < 8; k++) {
            float af[8], bf[TN];
            #pragma unroll
            for (int i = 0; i < 8; i++) af[i] = As[k][ty * 8 + i];
            #pragma unroll
            for (int j = 0; j < TN; j++) bf[j] = Bs[k][tx * TN + j];
            #pragma unroll
            for (int i = 0; i < 8; i++)
                #pragma unroll
                for (int j = 0; j < TN; j++)
                    acc[i][j] = fmaf(af[i], bf[j], acc[i][j]);
        }
        if (!has) break;
        __syncthreads();
        sts();
        __syncthreads();
    }

    // epilogue: bias (+relu for fc0), store, fused stats
    float bv[TN];
    #pragma unroll
    for (int j = 0; j < TN; j++) {
        int c = col0 + tx * TN + j;
        bv[j] = (c < Nc) ? bias[c] : 0.f;
    }
    #pragma unroll
    for (int i = 0; i < 8; i++) {
        int row = row0 + ty * 8 + i;
        bool vr = row < M;
        #pragma unroll
        for (int j = 0; j < TN; j++) {
            int c = col0 + tx * TN + j;
            float v = acc[i][j] + bv[j];
            if (FC0) v = fmaxf(v, 0.f);
            if (vr && c < Nc) C[(size_t)row * Nc + c] = v;
            acc[i][j] = vr ? v : 0.f;
        }
    }
    if (!FC0) {
        float s_[TN], q_[TN];
        #pragma unroll
        for (int j = 0; j < TN; j++) {
            float s = 0.f, q = 0.f;
            #pragma unroll
            for (int i = 0; i < 8; i++) { s += acc[i][j]; q = fmaf(acc[i][j], acc[i][j], q); }
            s_[j] = s; q_[j] = q;
        }
        __syncthreads();
        #pragma unroll
        for (int j = 0; j < TN; j++) red[ty][tx * TN + j] = s_[j];
        __syncthreads();
        if (ty == 0) {
            #pragma unroll
            for (int j = 0; j < TN; j++) {
                float t = 0.f;
                for (int u = 0; u < 16; u++) t += red[u][tx * TN + j];
                int c = col0 + tx * TN + j;
                if (c < Nc) atomicAdd(&g_sum[c], t);
            }
        }
        __syncthreads();
        #pragma unroll
        for (int j = 0; j < TN; j++) red[ty][tx * TN + j] = q_[j];
        __syncthreads();
        if (ty == 0) {
            #pragma unroll
            for (int j = 0; j < TN; j++) {
                float t = 0.f;
                for (int u = 0; u < 16; u++) t += red[u][tx * TN + j];
                int c = col0 + tx * TN + j;
                if (c < Nc) atomicAdd(&g_sq[c], t);
            }
        }
    }
}

// ---------------- BN finalize: compute scale/shift, reset sums ----------------
__global__ void k_finalize(const float* __restrict__ gamma, const float* __restrict__ beta,
                           int M, int Nc) {
    int c = threadIdx.x;
    if (c < Nc) {
        float inv = 1.f / (float)M;
        float mean = g_sum[c] * inv;
        float var = g_sq[c] * inv - mean * mean;
        float r = rsqrtf(var + 1e-5f);
        float a = gamma[c] * r;
        g_scale[c] = a;
        g_shift[c] = beta[c] - mean * a;
    }
    g_sum[c] = 0.f;
    g_sq[c] = 0.f;
}

// ---------------- pooling & head ----------------
__global__ void k_bounds(const int* __restrict__ batch, int n, int nb) {
    int g = threadIdx.x;
    if (g > nb) return;
    int lo = 0, hi = n;
    while (lo < hi) {
        int mid = (lo + hi) >> 1;
        if (batch[mid] < g) lo = mid + 1; else hi = mid;
    }
    g_starts[g] = lo;
}

__global__ void k_segmax() {   // reads g_x (N x 128)
    __shared__ float sh[4][128];
    int g = blockIdx.x, c = threadIdx.x, s = threadIdx.y;
    int beg = g_starts[g], end = g_starts[g + 1];
    float m = -3.4e38f;
    for (int r = beg + s; r < end; r += 4)
        m = fmaxf(m, g_x[(size_t)r * 128 + c]);
    sh[s][c] = m;
    __syncthreads();
    if (s == 0) {
        m = fmaxf(fmaxf(sh[0][c], sh[1][c]), fmaxf(sh[2][c], sh[3][c]));
        g_pool[g * 128 + c] = m;
    }
}

__global__ void k_head(const float* __restrict__ W1, const float* __restrict__ b1,
                       const float* __restrict__ W2, const float* __restrict__ b2,
                       const float* __restrict__ W3, const float* __restrict__ b3,
                       float* __restrict__ out) {
    __shared__ float xs[128];
    __shared__ float red[128];
    int g = blockIdx.x, c = threadIdx.x;
    xs[c] = g_pool[g * 128 + c];
    __syncthreads();

    float v = b1[c];
    #pragma unroll 8
    for (int k = 0; k < 128; k++) v = fmaf(xs[k], W1[k * 128 + c], v);
    v = fmaxf(v, 0.f);
    __syncthreads(); xs[c] = v; __syncthreads();

    v = b2[c];
    #pragma unroll 8
    for (int k = 0; k < 128; k++) v = fmaf(xs[k], W2[k * 128 + c], v);
    v = fmaxf(v, 0.f);
    __syncthreads(); xs[c] = v; __syncthreads();

    float v3 = b3[c];
    #pragma unroll 8
    for (int k = 0; k < 128; k++) v3 = fmaf(xs[k], W3[k * 128 + c], v3);

    red[c] = v3 * v3;
    __syncthreads();
    for (int off = 64; off > 0; off >>= 1) {
        if (c < off) red[c] += red[c + off];
        __syncthreads();
    }
    float nrm = fmaxf(sqrtf(red[0]), 1e-12f);
    out[g * 128 + c] = v3 / nrm;
}

// ---------------- host launch: kernel launches ONLY ----------------
extern "C" void kernel_launch(void* const* d_in, const int* in_sizes, int n_in,
                              void* d_out, int out_size) {
    const float* pos = (const float*)d_in[0];
    const int* ei = (const int*)d_in[1];
    const int* batch = (const int*)d_in[2];
    int n = in_sizes[0] / 3;
    int e = in_sizes[1] / 2;
    const int* src = ei;
    const int* dst = ei + e;
    float* out = (float*)d_out;

    const float *W[5], *bb[5], *gg[5], *be[5];
    for (int l = 0; l < 5; l++) {
        W[l]  = (const float*)d_in[3 + 4 * l];
        bb[l] = (const float*)d_in[4 + 4 * l];
        gg[l] = (const float*)d_in[5 + 4 * l];
        be[l] = (const float*)d_in[6 + 4 * l];
    }
    const float* fc0_W = (const float*)d_in[23];
    const float* fc0_b = (const float*)d_in[24];
    const float* fc1_W = (const float*)d_in[25];
    const float* fc1_b = (const float*)d_in[26];
    const float* fc2_W = (const float*)d_in[27];
    const float* fc2_b = (const float*)d_in[28];
    const float* fc3_W = (const float*)d_in[29];
    const float* fc3_b = (const float*)d_in[30];

    // ---- graph preprocessing ----
    k_zero<<<(n + 255) / 256, 256>>>(n);
    k_hist<<<(e + 255) / 256, 256>>>(dst, e);
    k_dinv<<<(n + 255) / 256, 256>>>(n);
    int nb = (n + 1023) / 1024;
    k_scan1<<<nb, 1024>>>(n);
    k_scan2<<<1, 32>>>(nb, n);
    k_scan3<<<nb, 1024>>>(n);
    k_place<<<(e + 255) / 256, 256>>>(src, dst, e);

    int aggBlocks = (n + 7) / 8;
    int rowBlocks = (n + 127) / 128;

    // ---- layer 1: 3 -> 16 ----
    k_agg<0><<<aggBlocks, 256>>>(pos, n, 3);
    k_gemm_s<3, 16><<<(n + 255) / 256, 256>>>(W[0], bb[0], n);
    k_finalize<<<1, 256>>>(gg[0], be[0], n, 16);

    // ---- layer 2: 16 -> 32 ----
    k_agg<1><<<aggBlocks, 256>>>(nullptr, n, 16);
    k_gemm_s<16, 32><<<(n + 255) / 256, 256>>>(W[1], bb[1], n);
    k_finalize<<<1, 256>>>(gg[1], be[1], n, 32);

    // ---- layer 3: 32 -> 64 ----
    k_agg<1><<<aggBlocks, 256>>>(nullptr, n, 32);
    k_gemm_t<4, 0><<<dim3(1, rowBlocks), 256>>>(W[2], bb[2], n, 32, 64);
    k_finalize<<<1, 256>>>(gg[2], be[2], n, 64);

    // ---- layer 4: 64 -> 94 ----
    k_agg<1><<<aggBlocks, 256>>>(nullptr, n, 64);
    k_gemm_t<6, 0><<<dim3(1, rowBlocks), 256>>>(W[3], bb[3], n, 64, 94);
    k_finalize<<<1, 256>>>(gg[3], be[3], n, 94);

    // ---- layer 5: 94 -> 256 ----
    k_agg<1><<<aggBlocks, 256>>>(nullptr, n, 94);
    k_gemm_t<8, 0><<<dim3(2, rowBlocks), 256>>>(W[4], bb[4], n, 94, 256);
    k_finalize<<<1, 256>>>(gg[4], be[4], n, 256);

    // ---- fc0: relu(bn(g_y)) @ W (256 -> 128) + relu, into g_x ----
    k_gemm_t<8, 1><<<dim3(1, rowBlocks), 256>>>(fc0_W, fc0_b, n, 256, 128);

    // ---- segment max pool + head MLP + normalize ----
    k_bounds<<<1, 65>>>(batch, n, 64);
    k_segmax<<<64, dim3(128, 4)>>>();
    k_head<<<64, 128>>>(fc1_W, fc1_b, fc2_W, fc2_b, fc3_W, fc3_b, out);
}

// round 4
// speedup vs baseline: 1.1284x; 1.1284x over previous
#include <cuda_runtime.h>
#include <math.h>

// ---------------- static scratch (no allocation allowed) ----------------
#define N_MAX 150016
#define E_MAX 900032

__device__ float g_y[(size_t)N_MAX * 256];   // GEMM output (pre-BN)
__device__ float g_z[(size_t)N_MAX * 96];    // aggregated input features
__device__ float g_x[(size_t)N_MAX * 128];   // fc0 output
__device__ int   g_deg[N_MAX];
__device__ int   g_cursor[N_MAX];
__device__ int   g_rowptr[N_MAX + 1];        // block-local exclusive scan
__device__ int   g_csr_src[E_MAX];
__device__ float g_csr_w[E_MAX];
__device__ float g_dinv[N_MAX];
__device__ float g_cs[N_MAX];
__device__ int   g_blocksum[256];
__device__ int   g_blockoff[257];
__device__ float g_sum[256];
__device__ float g_sq[256];
__device__ float g_scale[256];
__device__ float g_shift[256];
__device__ float g_pool[64 * 128];
__device__ int   g_starts[65];

// ---------------- prep kernels ----------------
__global__ void k_zero(int n) {
    int i = blockIdx.x * blockDim.x + threadIdx.x;
    if (i < n) { g_deg[i] = 0; g_cursor[i] = 0; }
    if (i < 256) { g_sum[i] = 0.f; g_sq[i] = 0.f; }
}

__global__ void k_hist(const int* __restrict__ dst, int e) {
    int i = blockIdx.x * blockDim.x + threadIdx.x;
    if (i < e) atomicAdd(&g_deg[dst[i]], 1);
}

// block-local exclusive scan of degrees + dinv/cs computation
__global__ void k_scan1(int n) {
    __shared__ int sh[1024];
    int t = threadIdx.x;
    int idx = blockIdx.x * 1024 + t;
    int v = (idx < n) ? g_deg[idx] : 0;
    sh[t] = v;
    __syncthreads();
    for (int off = 1; off < 1024; off <<= 1) {
        int add = (t >= off) ? sh[t - off] : 0;
        __syncthreads();
        sh[t] += add;
        __syncthreads();
    }
    if (idx < n) {
        g_rowptr[idx] = sh[t] - v;           // block-local exclusive
        float d = (float)(v + 1);
        float r = rsqrtf(d);
        g_dinv[idx] = r;
        g_cs[idx] = r * r;
    }
    if (t == 1023) g_blocksum[blockIdx.x] = sh[t];
}

__global__ void k_scan2(int nb, int n) {
    if (threadIdx.x == 0) {
        int run = 0;
        for (int i = 0; i < nb; i++) { g_blockoff[i] = run; run += g_blocksum[i]; }
        g_blockoff[nb] = run;
        int bi = n >> 10;
        g_rowptr[n] = run - g_blockoff[bi];  // so rowptr[n]+blockoff[n>>10] == E
    }
}

__device__ __forceinline__ int rp(int i) {   // global rowptr
    return g_rowptr[i] + g_blockoff[i >> 10];
}

__global__ void k_place(const int* __restrict__ src, const int* __restrict__ dst, int e) {
    int i = blockIdx.x * blockDim.x + threadIdx.x;
    if (i < e) {
        int d = dst[i], s = src[i];
        int p = rp(d) + atomicAdd(&g_cursor[d], 1);
        g_csr_src[p] = s;
        g_csr_w[p] = g_dinv[s] * g_dinv[d];
    }
}

// ---------------- aggregation (fused BN+ReLU on input) ----------------
// MODE 0: input = xext (raw pos). MODE 1: input = relu(bn(g_y)).
// Warp per node; lanes = channels (up to 96). Edge meta: broadcast loads.
template<int MODE>
__global__ void k_agg(const float* __restrict__ xext, int n, int din) {
    const float* __restrict__ x = (MODE == 0) ? xext : g_y;
    int gt = blockIdx.x * blockDim.x + threadIdx.x;
    int node = gt >> 5;
    int lane = gt & 31;
    if (node >= n) return;
    int c0 = lane, c1 = lane + 32, c2 = lane + 64;
    bool v0 = c0 < din, v1 = c1 < din, v2 = c2 < din;
    float s0 = 1.f, h0 = 0.f, s1 = 1.f, h1 = 0.f, s2 = 1.f, h2 = 0.f;
    if (MODE) {
        if (v0) { s0 = g_scale[c0]; h0 = g_shift[c0]; }
        if (v1) { s1 = g_scale[c1]; h1 = g_shift[c1]; }
        if (v2) { s2 = g_scale[c2]; h2 = g_shift[c2]; }
    }
    int beg = rp(node), end = rp(node + 1);
    float a0 = 0.f, a1 = 0.f, a2 = 0.f;
    for (int p = beg; p < end; p++) {
        int s = g_csr_src[p];
        float w = g_csr_w[p];
        const float* xs = x + (size_t)s * din;
        if (v0) { float v = xs[c0]; if (MODE) v = fmaxf(fmaf(v, s0, h0), 0.f); a0 = fmaf(v, w, a0); }
        if (v1) { float v = xs[c1]; if (MODE) v = fmaxf(fmaf(v, s1, h1), 0.f); a1 = fmaf(v, w, a1); }
        if (v2) { float v = xs[c2]; if (MODE) v = fmaxf(fmaf(v, s2, h2), 0.f); a2 = fmaf(v, w, a2); }
    }
    float cw = g_cs[node];
    const float* xi = x + (size_t)node * din;
    float* zi = g_z + (size_t)node * din;
    if (v0) { float v = xi[c0]; if (MODE) v = fmaxf(fmaf(v, s0, h0), 0.f); zi[c0] = fmaf(v, cw, a0); }
    if (v1) { float v = xi[c1]; if (MODE) v = fmaxf(fmaf(v, s1, h1), 0.f); zi[c1] = fmaf(v, cw, a1); }
    if (v2) { float v = xi[c2]; if (MODE) v = fmaxf(fmaf(v, s2, h2), 0.f); zi[c2] = fmaf(v, cw, a2); }
}

// ---------------- small GEMM (K<=16, NC<=32): thread per row, fused stats ----
template<int K, int NC>
__global__ __launch_bounds__(256) void k_gemm_s(
    const float* __restrict__ Bm, const float* __restrict__ bias, int M)
{
    __shared__ float Ws[K * NC];
    __shared__ float bs[NC];
    int tid = threadIdx.x;
    for (int i = tid; i < K * NC; i += 256) Ws[i] = Bm[i];
    if (tid < NC) bs[tid] = bias[tid];
    __syncthreads();

    int r = blockIdx.x * 256 + tid;
    bool valid = r < M;
    float a[K];
    #pragma unroll
    for (int k = 0; k < K; k++) a[k] = valid ? g_z[(size_t)r * K + k] : 0.f;
    float acc[NC];
    #pragma unroll
    for (int c = 0; c < NC; c++) acc[c] = valid ? bs[c] : 0.f;
    #pragma unroll
    for (int k = 0; k < K; k++)
        #pragma unroll
        for (int c = 0; c < NC; c++) acc[c] = fmaf(a[k], Ws[k * NC + c], acc[c]);

    if (valid) {
        float4* dst = (float4*)(g_y + (size_t)r * NC);
        #pragma unroll
        for (int c = 0; c < NC; c += 4)
            dst[c >> 2] = make_float4(acc[c], acc[c + 1], acc[c + 2], acc[c + 3]);
    }
    float q[NC];
    #pragma unroll
    for (int c = 0; c < NC; c++) q[c] = acc[c] * acc[c];
    #pragma unroll
    for (int off = 16; off; off >>= 1) {
        #pragma unroll
        for (int c = 0; c < NC; c++) {
            acc[c] += __shfl_down_sync(0xffffffffu, acc[c], off);
            q[c]   += __shfl_down_sync(0xffffffffu, q[c], off);
        }
    }
    if ((tid & 31) == 0) {
        #pragma unroll
        for (int c = 0; c < NC; c++) {
            atomicAdd(&g_sum[c], acc[c]);
            atomicAdd(&g_sq[c], q[c]);
        }
    }
}

// ---------------- tiled SGEMM 128x64x16, 8x4/thread (R2-proven body) -------
// FC0==0: g_y = g_z @ W + b, fused stats.
// FC0==1: g_x = relu( relu(bn(g_y)) @ W + b ), no stats.
#define BM 128
#define BN 64
#define BK 16
template<int FC0>
__global__ __launch_bounds__(256) void k_gemm(
    const float* __restrict__ Bm, const float* __restrict__ bias,
    int M, int K, int Nc)
{
    const float* __restrict__ A = FC0 ? g_y : g_z;
    float* __restrict__ C = FC0 ? g_x : g_y;
    __shared__ float As[BK][BM + 4];
    __shared__ float Bs[BK][BN];
    __shared__ float red[16][BN];
    __shared__ float sbn_s[256], sbn_h[256];
    int tid = threadIdx.x;
    int tx = tid & 15;      // 0..15 -> cols
    int ty = tid >> 4;      // 0..15 -> rows
    int row0 = blockIdx.y * BM;
    int col0 = blockIdx.x * BN;

    if (FC0) {
        for (int i = tid; i < K; i += 256) { sbn_s[i] = g_scale[i]; sbn_h[i] = g_shift[i]; }
        __syncthreads();
    }

    float acc[8][4];
    #pragma unroll
    for (int i = 0; i < 8; i++)
        #pragma unroll
        for (int j = 0; j < 4; j++) acc[i][j] = 0.f;

    for (int k0 = 0; k0 < K; k0 += BK) {
        #pragma unroll
        for (int j = 0; j < 8; j++) {
            int r = (tid >> 4) + j * 16;
            int gk = k0 + (tid & 15);
            float v = 0.f;
            if (row0 + r < M && gk < K) {
                v = A[(size_t)(row0 + r) * K + gk];
                if (FC0) v = fmaxf(fmaf(v, sbn_s[gk], sbn_h[gk]), 0.f);
            }
            As[tid & 15][r] = v;
        }
        #pragma unroll
        for (int j = 0; j < 4; j++) {
            int kk = (tid >> 6) + j * 4;
            int nn = tid & 63;
            float v = 0.f;
            int gk = k0 + kk;
            if (gk < K && col0 + nn < Nc) v = Bm[(size_t)gk * Nc + col0 + nn];
            Bs[kk][nn] = v;
        }
        __syncthreads();
        #pragma unroll
        for (int k = 0; k < BK; k++) {
            float af[8], bf[4];
            #pragma unroll
            for (int i = 0; i < 8; i++) af[i] = As[k][ty * 8 + i];
            #pragma unroll
            for (int j = 0; j < 4; j++) bf[j] = Bs[k][tx * 4 + j];
            #pragma unroll
            for (int i = 0; i < 8; i++)
                #pragma unroll
                for (int j = 0; j < 4; j++)
                    acc[i][j] = fmaf(af[i], bf[j], acc[i][j]);
        }
        __syncthreads();
    }

    // epilogue: bias (+relu for fc0), store, keep post-bias values for stats
    float bv[4];
    #pragma unroll
    for (int j = 0; j < 4; j++) {
        int c = col0 + tx * 4 + j;
        bv[j] = (c < Nc) ? bias[c] : 0.f;
    }
    #pragma unroll
    for (int i = 0; i < 8; i++) {
        int r = row0 + ty * 8 + i;
        bool vr = r < M;
        #pragma unroll
        for (int j = 0; j < 4; j++) {
            int c = col0 + tx * 4 + j;
            float v = acc[i][j] + bv[j];
            if (FC0) v = fmaxf(v, 0.f);
            if (vr && c < Nc) C[(size_t)r * Nc + c] = v;
            acc[i][j] = vr ? v : 0.f;
        }
    }
    if (!FC0) {
        float s_[4], q_[4];
        #pragma unroll
        for (int j = 0; j < 4; j++) {
            float s = 0.f, q = 0.f;
            #pragma unroll
            for (int i = 0; i < 8; i++) { s += acc[i][j]; q = fmaf(acc[i][j], acc[i][j], q); }
            s_[j] = s; q_[j] = q;
        }
        __syncthreads();
        #pragma unroll
        for (int j = 0; j < 4; j++) red[ty][tx * 4 + j] = s_[j];
        __syncthreads();
        if (ty == 0) {
            #pragma unroll
            for (int j = 0; j < 4; j++) {
                float t = 0.f;
                #pragma unroll
                for (int u = 0; u < 16; u++) t += red[u][tx * 4 + j];
                int c = col0 + tx * 4 + j;
                if (c < Nc) atomicAdd(&g_sum[c], t);
            }
        }
        __syncthreads();
        #pragma unroll
        for (int j = 0; j < 4; j++) red[ty][tx * 4 + j] = q_[j];
        __syncthreads();
        if (ty == 0) {
            #pragma unroll
            for (int j = 0; j < 4; j++) {
                float t = 0.f;
                #pragma unroll
                for (int u = 0; u < 16; u++) t += red[u][tx * 4 + j];
                int c = col0 + tx * 4 + j;
                if (c < Nc) atomicAdd(&g_sq[c], t);
            }
        }
    }
}

// ---------------- BN finalize: scale/shift; reset accumulators -------------
__global__ void k_finalize(const float* __restrict__ gamma, const float* __restrict__ beta,
                           int M, int Nc) {
    int c = threadIdx.x;
    if (c < Nc) {
        float inv = 1.f / (float)M;
        float mean = g_sum[c] * inv;
        float var = g_sq[c] * inv - mean * mean;
        float r = rsqrtf(var + 1e-5f);
        float a = gamma[c] * r;
        g_scale[c] = a;
        g_shift[c] = beta[c] - mean * a;
    }
    g_sum[c] = 0.f;
    g_sq[c] = 0.f;
}

// ---------------- pooling & head ----------------
__global__ void k_bounds(const int* __restrict__ batch, int n, int nb) {
    int g = threadIdx.x;
    if (g > nb) return;
    int lo = 0, hi = n;
    while (lo < hi) {
        int mid = (lo + hi) >> 1;
        if (batch[mid] < g) lo = mid + 1; else hi = mid;
    }
    g_starts[g] = lo;
}

__global__ void k_segmax() {   // reads g_x (N x 128)
    __shared__ float sh[4][128];
    int g = blockIdx.x, c = threadIdx.x, s = threadIdx.y;
    int beg = g_starts[g], end = g_starts[g + 1];
    float m = -3.4e38f;
    for (int r = beg + s; r < end; r += 4)
        m = fmaxf(m, g_x[(size_t)r * 128 + c]);
    sh[s][c] = m;
    __syncthreads();
    if (s == 0) {
        m = fmaxf(fmaxf(sh[0][c], sh[1][c]), fmaxf(sh[2][c], sh[3][c]));
        g_pool[g * 128 + c] = m;
    }
}

__global__ void k_head(const float* __restrict__ W1, const float* __restrict__ b1,
                       const float* __restrict__ W2, const float* __restrict__ b2,
                       const float* __restrict__ W3, const float* __restrict__ b3,
                       float* __restrict__ out) {
    __shared__ float xs[128];
    __shared__ float red[128];
    int g = blockIdx.x, c = threadIdx.x;
    xs[c] = g_pool[g * 128 + c];
    __syncthreads();

    float v = b1[c];
    #pragma unroll 8
    for (int k = 0; k < 128; k++) v = fmaf(xs[k], W1[k * 128 + c], v);
    v = fmaxf(v, 0.f);
    __syncthreads(); xs[c] = v; __syncthreads();

    v = b2[c];
    #pragma unroll 8
    for (int k = 0; k < 128; k++) v = fmaf(xs[k], W2[k * 128 + c], v);
    v = fmaxf(v, 0.f);
    __syncthreads(); xs[c] = v; __syncthreads();

    float v3 = b3[c];
    #pragma unroll 8
    for (int k = 0; k < 128; k++) v3 = fmaf(xs[k], W3[k * 128 + c], v3);

    red[c] = v3 * v3;
    __syncthreads();
    for (int off = 64; off > 0; off >>= 1) {
        if (c < off) red[c] += red[c + off];
        __syncthreads();
    }
    float nrm = fmaxf(sqrtf(red[0]), 1e-12f);
    out[g * 128 + c] = v3 / nrm;
}

// ---------------- host launch: kernel launches ONLY ----------------
extern "C" void kernel_launch(void* const* d_in, const int* in_sizes, int n_in,
                              void* d_out, int out_size) {
    const float* pos = (const float*)d_in[0];
    const int* ei = (const int*)d_in[1];
    const int* batch = (const int*)d_in[2];
    int n = in_sizes[0] / 3;
    int e = in_sizes[1] / 2;
    const int* src = ei;
    const int* dst = ei + e;
    float* out = (float*)d_out;

    const float *W[5], *bb[5], *gg[5], *be[5];
    for (int l = 0; l < 5; l++) {
        W[l]  = (const float*)d_in[3 + 4 * l];
        bb[l] = (const float*)d_in[4 + 4 * l];
        gg[l] = (const float*)d_in[5 + 4 * l];
        be[l] = (const float*)d_in[6 + 4 * l];
    }
    const float* fc0_W = (const float*)d_in[23];
    const float* fc0_b = (const float*)d_in[24];
    const float* fc1_W = (const float*)d_in[25];
    const float* fc1_b = (const float*)d_in[26];
    const float* fc2_W = (const float*)d_in[27];
    const float* fc2_b = (const float*)d_in[28];
    const float* fc3_W = (const float*)d_in[29];
    const float* fc3_b = (const float*)d_in[30];

    // ---- graph preprocessing (5 launches) ----
    k_zero<<<(n + 255) / 256, 256>>>(n);
    k_hist<<<(e + 255) / 256, 256>>>(dst, e);
    int nb = (n + 1023) / 1024;
    k_scan1<<<nb, 1024>>>(n);
    k_scan2<<<1, 32>>>(nb, n);
    k_place<<<(e + 255) / 256, 256>>>(src, dst, e);

    int aggBlocks = (n + 7) / 8;
    int rowBlocks = (n + BM - 1) / BM;

    // ---- layer 1: 3 -> 16 ----
    k_agg<0><<<aggBlocks, 256>>>(pos, n, 3);
    k_gemm_s<3, 16><<<(n + 255) / 256, 256>>>(W[0], bb[0], n);
    k_finalize<<<1, 256>>>(gg[0], be[0], n, 16);

    // ---- layer 2: 16 -> 32 ----
    k_agg<1><<<aggBlocks, 256>>>(nullptr, n, 16);
    k_gemm_s<16, 32><<<(n + 255) / 256, 256>>>(W[1], bb[1], n);
    k_finalize<<<1, 256>>>(gg[1], be[1], n, 32);

    // ---- layer 3: 32 -> 64 ----
    k_agg<1><<<aggBlocks, 256>>>(nullptr, n, 32);
    k_gemm<0><<<dim3(1, rowBlocks), 256>>>(W[2], bb[2], n, 32, 64);
    k_finalize<<<1, 256>>>(gg[2], be[2], n, 64);

    // ---- layer 4: 64 -> 94 ----
    k_agg<1><<<aggBlocks, 256>>>(nullptr, n, 64);
    k_gemm<0><<<dim3(2, rowBlocks), 256>>>(W[3], bb[3], n, 64, 94);
    k_finalize<<<1, 256>>>(gg[3], be[3], n, 94);

    // ---- layer 5: 94 -> 256 ----
    k_agg<1><<<aggBlocks, 256>>>(nullptr, n, 94);
    k_gemm<0><<<dim3(4, rowBlocks), 256>>>(W[4], bb[4], n, 94, 256);
    k_finalize<<<1, 256>>>(gg[4], be[4], n, 256);

    // ---- fc0: relu(bn(g_y)) @ W (256 -> 128) + relu, into g_x ----
    k_gemm<1><<<dim3(2, rowBlocks), 256>>>(fc0_W, fc0_b, n, 256, 128);

    // ---- segment max pool + head MLP + normalize ----
    k_bounds<<<1, 65>>>(batch, n, 64);
    k_segmax<<<64, dim3(128, 4)>>>();
    k_head<<<64, 128>>>(fc1_W, fc1_b, fc2_W, fc2_b, fc3_W, fc3_b, out);
}

// round 6
// speedup vs baseline: 1.2276x; 1.0879x over previous
#include <cuda_runtime.h>
#include <math.h>

// ---------------- static scratch (no allocation allowed) ----------------
#define N_MAX 150016
#define E_MAX 900032

__device__ float g_y[(size_t)N_MAX * 256];   // GEMM output (pre-BN)
__device__ float g_z[(size_t)N_MAX * 96];    // aggregated input features
__device__ float g_x[(size_t)N_MAX * 128];   // fc0 output
__device__ int   g_deg[N_MAX];
__device__ int   g_cursor[N_MAX];
__device__ int   g_rowptr[N_MAX + 1];        // block-local exclusive scan
__device__ int   g_csr_src[E_MAX];
__device__ float g_csr_w[E_MAX];
__device__ float g_dinv[N_MAX];
__device__ float g_cs[N_MAX];
__device__ int   g_blocksum[256];
__device__ int   g_blockoff[257];
__device__ float g_sum[256];
__device__ float g_sq[256];
__device__ float g_scale[256];
__device__ float g_shift[256];
__device__ float g_pool[64 * 128];
__device__ int   g_starts[65];

// ---------------- f32x2 helpers ----------------
__device__ __forceinline__ void fma2(unsigned long long& acc,
                                     unsigned long long a, unsigned long long b) {
    asm("fma.rn.f32x2 %0, %1, %2, %0;" : "+l"(acc) : "l"(a), "l"(b));
}
__device__ __forceinline__ unsigned long long pack2(float lo, float hi) {
    unsigned long long r;
    asm("mov.b64 %0, {%1, %2};" : "=l"(r) : "f"(lo), "f"(hi));
    return r;
}
__device__ __forceinline__ float2 unpack2(unsigned long long v) {
    float2 r;
    asm("mov.b64 {%0, %1}, %2;" : "=f"(r.x), "=f"(r.y) : "l"(v));
    return r;
}

// ---------------- prep kernels ----------------
__global__ void k_zero(int n) {
    int i = blockIdx.x * blockDim.x + threadIdx.x;
    if (i < n) { g_deg[i] = 0; g_cursor[i] = 0; }
    if (i < 256) { g_sum[i] = 0.f; g_sq[i] = 0.f; }
}

__global__ void k_hist(const int* __restrict__ dst, int e) {
    int i = blockIdx.x * blockDim.x + threadIdx.x;
    if (i < e) atomicAdd(&g_deg[dst[i]], 1);
}

// block-local exclusive scan of degrees + dinv/cs computation
__global__ void k_scan1(int n) {
    __shared__ int sh[1024];
    int t = threadIdx.x;
    int idx = blockIdx.x * 1024 + t;
    int v = (idx < n) ? g_deg[idx] : 0;
    sh[t] = v;
    __syncthreads();
    for (int off = 1; off < 1024; off <<= 1) {
        int add = (t >= off) ? sh[t - off] : 0;
        __syncthreads();
        sh[t] += add;
        __syncthreads();
    }
    if (idx < n) {
        g_rowptr[idx] = sh[t] - v;           // block-local exclusive
        float d = (float)(v + 1);
        float r = rsqrtf(d);
        g_dinv[idx] = r;
        g_cs[idx] = r * r;
    }
    if (t == 1023) g_blocksum[blockIdx.x] = sh[t];
}

// parallel scan of block sums (nb <= 256)
__global__ void k_scan2(int nb, int n) {
    __shared__ int sh[256];
    int t = threadIdx.x;
    int v = (t < nb) ? g_blocksum[t] : 0;
    sh[t] = v;
    __syncthreads();
    for (int off = 1; off < 256; off <<= 1) {
        int add = (t >= off) ? sh[t - off] : 0;
        __syncthreads();
        sh[t] += add;
        __syncthreads();
    }
    int total = sh[255];
    if (t < nb) g_blockoff[t] = sh[t] - v;
    if (t == nb) g_blockoff[nb] = total;
    if (t == (n >> 10)) g_rowptr[n] = total - (sh[t] - v); // rp(n) == E
}

__device__ __forceinline__ int rp(int i) {   // global rowptr
    return g_rowptr[i] + g_blockoff[i >> 10];
}

__global__ void k_place(const int* __restrict__ src, const int* __restrict__ dst, int e) {
    int i = blockIdx.x * blockDim.x + threadIdx.x;
    if (i < e) {
        int d = dst[i], s = src[i];
        int p = rp(d) + atomicAdd(&g_cursor[d], 1);
        g_csr_src[p] = s;
        g_csr_w[p] = g_dinv[s] * g_dinv[d];
    }
}

// ---------------- aggregation (fused BN+ReLU on input) ----------------
template<int MODE>
__global__ void k_agg(const float* __restrict__ xext, int n, int din) {
    const float* __restrict__ x = (MODE == 0) ? xext : g_y;
    int gt = blockIdx.x * blockDim.x + threadIdx.x;
    int node = gt >> 5;
    int lane = gt & 31;
    if (node >= n) return;
    int c0 = lane, c1 = lane + 32, c2 = lane + 64;
    bool v0 = c0 < din, v1 = c1 < din, v2 = c2 < din;
    float s0 = 1.f, h0 = 0.f, s1 = 1.f, h1 = 0.f, s2 = 1.f, h2 = 0.f;
    if (MODE) {
        if (v0) { s0 = g_scale[c0]; h0 = g_shift[c0]; }
        if (v1) { s1 = g_scale[c1]; h1 = g_shift[c1]; }
        if (v2) { s2 = g_scale[c2]; h2 = g_shift[c2]; }
    }
    int beg = rp(node), end = rp(node + 1);
    float a0 = 0.f, a1 = 0.f, a2 = 0.f;
    for (int p = beg; p < end; p++) {
        int s = g_csr_src[p];
        float w = g_csr_w[p];
        const float* xs = x + (size_t)s * din;
        if (v0) { float v = xs[c0]; if (MODE) v = fmaxf(fmaf(v, s0, h0), 0.f); a0 = fmaf(v, w, a0); }
        if (v1) { float v = xs[c1]; if (MODE) v = fmaxf(fmaf(v, s1, h1), 0.f); a1 = fmaf(v, w, a1); }
        if (v2) { float v = xs[c2]; if (MODE) v = fmaxf(fmaf(v, s2, h2), 0.f); a2 = fmaf(v, w, a2); }
    }
    float cw = g_cs[node];
    const float* xi = x + (size_t)node * din;
    float* zi = g_z + (size_t)node * din;
    if (v0) { float v = xi[c0]; if (MODE) v = fmaxf(fmaf(v, s0, h0), 0.f); zi[c0] = fmaf(v, cw, a0); }
    if (v1) { float v = xi[c1]; if (MODE) v = fmaxf(fmaf(v, s1, h1), 0.f); zi[c1] = fmaf(v, cw, a1); }
    if (v2) { float v = xi[c2]; if (MODE) v = fmaxf(fmaf(v, s2, h2), 0.f); zi[c2] = fmaf(v, cw, a2); }
}

// ---------------- small GEMM (K<=16, NC<=32): thread per row, fused stats ----
template<int K, int NC>
__global__ __launch_bounds__(256) void k_gemm_s(
    const float* __restrict__ Bm, const float* __restrict__ bias, int M)
{
    __shared__ float Ws[K * NC];
    __shared__ float bs[NC];
    int tid = threadIdx.x;
    for (int i = tid; i < K * NC; i += 256) Ws[i] = Bm[i];
    if (tid < NC) bs[tid] = bias[tid];
    __syncthreads();

    int r = blockIdx.x * 256 + tid;
    bool valid = r < M;
    float a[K];
    #pragma unroll
    for (int k = 0; k < K; k++) a[k] = valid ? g_z[(size_t)r * K + k] : 0.f;
    float acc[NC];
    #pragma unroll
    for (int c = 0; c < NC; c++) acc[c] = valid ? bs[c] : 0.f;
    #pragma unroll
    for (int k = 0; k < K; k++)
        #pragma unroll
        for (int c = 0; c < NC; c++) acc[c] = fmaf(a[k], Ws[k * NC + c], acc[c]);

    if (valid) {
        float4* dst = (float4*)(g_y + (size_t)r * NC);
        #pragma unroll
        for (int c = 0; c < NC; c += 4)
            dst[c >> 2] = make_float4(acc[c], acc[c + 1], acc[c + 2], acc[c + 3]);
    }
    float q[NC];
    #pragma unroll
    for (int c = 0; c < NC; c++) q[c] = acc[c] * acc[c];
    #pragma unroll
    for (int off = 16; off; off >>= 1) {
        #pragma unroll
        for (int c = 0; c < NC; c++) {
            acc[c] += __shfl_down_sync(0xffffffffu, acc[c], off);
            q[c]   += __shfl_down_sync(0xffffffffu, q[c], off);
        }
    }
    if ((tid & 31) == 0) {
        #pragma unroll
        for (int c = 0; c < NC; c++) {
            atomicAdd(&g_sum[c], acc[c]);
            atomicAdd(&g_sq[c], q[c]);
        }
    }
}

// ---------------- f32x2 tiled SGEMM: BLKM x BLKN, 256 threads, 8x8/thread ----
// FC0==0: g_y = g_z @ W + b (fused BN stats).
// FC0==1: g_x = relu( relu(bn(g_y)) @ W + b ), no stats.
// Thread (tx,tr): rows tr*8..tr*8+7, column-pairs (2tx+2*NTX*j, +1) j=0..3.
template<int BLKM, int BLKN, int FC0>
__global__ __launch_bounds__(256) void k_gemm2(
    const float* __restrict__ Bm, const float* __restrict__ bias,
    int M, int K, int Nc)
{
    constexpr int NTX = BLKN / 8;          // 8 or 16
    constexpr int NTY = 256 / NTX;         // 32 or 16
    constexpr int NLA = BLKM / 16;         // A-load reps per thread
    const float* __restrict__ A = FC0 ? g_y : g_z;
    float* __restrict__ C = FC0 ? g_x : g_y;

    __shared__ __align__(16) float As[16][BLKM + 4];
    __shared__ __align__(16) float Bs[16][BLKN];
    __shared__ float2 red2[NTY][BLKN];
    __shared__ float sbn_s[256], sbn_h[256];

    int tid = threadIdx.x;
    int tx = tid % NTX;
    int tr = tid / NTX;
    int row0 = blockIdx.y * BLKM;
    int col0 = blockIdx.x * BLKN;

    if (FC0) {
        for (int i = tid; i < K; i += 256) { sbn_s[i] = g_scale[i]; sbn_h[i] = g_shift[i]; }
        __syncthreads();
    }

    unsigned long long acc[8][4];
    #pragma unroll
    for (int i = 0; i < 8; i++)
        #pragma unroll
        for (int j = 0; j < 4; j++) acc[i][j] = 0ull;

    int la_k = tid & 15, la_r = tid >> 4;
    int lb_k0 = tid / BLKN, lb_n = tid % BLKN;   // B-load start coords
    constexpr int LBSTEP = 256 / BLKN;           // k rows per step (4 or 2)

    for (int k0 = 0; k0 < K; k0 += 16) {
        // A tile: 16 k x BLKM rows (coalesced over k)
        #pragma unroll
        for (int j = 0; j < NLA; j++) {
            int r = la_r + j * 16;
            int gk = k0 + la_k;
            float v = 0.f;
            if (row0 + r < M && gk < K) {
                v = A[(size_t)(row0 + r) * K + gk];
                if (FC0) v = fmaxf(fmaf(v, sbn_s[gk], sbn_h[gk]), 0.f);
            }
            As[la_k][r] = v;
        }
        // B tile: 16 k x BLKN cols (coalesced over n)
        #pragma unroll
        for (int kk = lb_k0; kk < 16; kk += LBSTEP) {
            int gk = k0 + kk, c = col0 + lb_n;
            Bs[kk][lb_n] = (gk < K && c < Nc) ? Bm[(size_t)gk * Nc + c] : 0.f;
        }
        __syncthreads();
        #pragma unroll
        for (int kk = 0; kk < 16; kk++) {
            float4 aLo = *(const float4*)&As[kk][tr * 8];
            float4 aHi = *(const float4*)&As[kk][tr * 8 + 4];
            unsigned long long a2[8];
            a2[0] = pack2(aLo.x, aLo.x); a2[1] = pack2(aLo.y, aLo.y);
            a2[2] = pack2(aLo.z, aLo.z); a2[3] = pack2(aLo.w, aLo.w);
            a2[4] = pack2(aHi.x, aHi.x); a2[5] = pack2(aHi.y, aHi.y);
            a2[6] = pack2(aHi.z, aHi.z); a2[7] = pack2(aHi.w, aHi.w);
            unsigned long long b2[4];
            #pragma unroll
            for (int j = 0; j < 4; j++)
                b2[j] = *(const unsigned long long*)&Bs[kk][2 * tx + 2 * NTX * j];
            #pragma unroll
            for (int i = 0; i < 8; i++)
                #pragma unroll
                for (int j = 0; j < 4; j++)
                    fma2(acc[i][j], a2[i], b2[j]);
        }
        __syncthreads();
    }

    // epilogue: bias (+relu for fc0), store, fused stats
    #pragma unroll
    for (int j = 0; j < 4; j++) {
        int lc = 2 * tx + 2 * NTX * j;
        int c = col0 + lc;
        float b0 = (c < Nc) ? bias[c] : 0.f;
        float b1 = (c + 1 < Nc) ? bias[c + 1] : 0.f;
        float s0 = 0.f, q0 = 0.f, s1 = 0.f, q1 = 0.f;
        #pragma unroll
        for (int i = 0; i < 8; i++) {
            int r = row0 + tr * 8 + i;
            float2 v = unpack2(acc[i][j]);
            v.x += b0; v.y += b1;
            if (FC0) { v.x = fmaxf(v.x, 0.f); v.y = fmaxf(v.y, 0.f); }
            if (r < M) {
                if (c < Nc)     C[(size_t)r * Nc + c] = v.x;
                if (c + 1 < Nc) C[(size_t)r * Nc + c + 1] = v.y;
                s0 += v.x; q0 = fmaf(v.x, v.x, q0);
                s1 += v.y; q1 = fmaf(v.y, v.y, q1);
            }
        }
        if (!FC0) {
            red2[tr][lc]     = make_float2(s0, q0);
            red2[tr][lc + 1] = make_float2(s1, q1);
        }
    }
    if (!FC0) {
        __syncthreads();
        if (tr == 0) {
            #pragma unroll
            for (int j = 0; j < 4; j++) {
                #pragma unroll
                for (int h = 0; h < 2; h++) {
                    int lc = 2 * tx + 2 * NTX * j + h;
                    float s = 0.f, q = 0.f;
                    for (int u = 0; u < NTY; u++) {
                        float2 t = red2[u][lc];
                        s += t.x; q += t.y;
                    }
                    int c = col0 + lc;
                    if (c < Nc) {
                        atomicAdd(&g_sum[c], s);
                        atomicAdd(&g_sq[c], q);
                    }
                }
            }
        }
    }
}

// ---------------- BN finalize: scale/shift; reset accumulators -------------
__global__ void k_finalize(const float* __restrict__ gamma, const float* __restrict__ beta,
                           int M, int Nc) {
    int c = threadIdx.x;
    if (c < Nc) {
        float inv = 1.f / (float)M;
        float mean = g_sum[c] * inv;
        float var = g_sq[c] * inv - mean * mean;
        float r = rsqrtf(var + 1e-5f);
        float a = gamma[c] * r;
        g_scale[c] = a;
        g_shift[c] = beta[c] - mean * a;
    }
    g_sum[c] = 0.f;
    g_sq[c] = 0.f;
}

// ---------------- pooling & head ----------------
__global__ void k_bounds(const int* __restrict__ batch, int n, int nb) {
    int g = threadIdx.x;
    if (g > nb) return;
    int lo = 0, hi = n;
    while (lo < hi) {
        int mid = (lo + hi) >> 1;
        if (batch[mid] < g) lo = mid + 1; else hi = mid;
    }
    g_starts[g] = lo;
}

__global__ void k_segmax() {   // reads g_x (N x 128)
    __shared__ float sh[4][128];
    int g = blockIdx.x, c = threadIdx.x, s = threadIdx.y;
    int beg = g_starts[g], end = g_starts[g + 1];
    float m = -3.4e38f;
    for (int r = beg + s; r < end; r += 4)
        m = fmaxf(m, g_x[(size_t)r * 128 + c]);
    sh[s][c] = m;
    __syncthreads();
    if (s == 0) {
        m = fmaxf(fmaxf(sh[0][c], sh[1][c]), fmaxf(sh[2][c], sh[3][c]));
        g_pool[g * 128 + c] = m;
    }
}

__global__ void k_head(const float* __restrict__ W1, const float* __restrict__ b1,
                       const float* __restrict__ W2, const float* __restrict__ b2,
                       const float* __restrict__ W3, const float* __restrict__ b3,
                       float* __restrict__ out) {
    __shared__ float xs[128];
    __shared__ float red[128];
    int g = blockIdx.x, c = threadIdx.x;
    xs[c] = g_pool[g * 128 + c];
    __syncthreads();

    float v = b1[c];
    #pragma unroll 8
    for (int k = 0; k < 128; k++) v = fmaf(xs[k], W1[k * 128 + c], v);
    v = fmaxf(v, 0.f);
    __syncthreads(); xs[c] = v; __syncthreads();

    v = b2[c];
    #pragma unroll 8
    for (int k = 0; k < 128; k++) v = fmaf(xs[k], W2[k * 128 + c], v);
    v = fmaxf(v, 0.f);
    __syncthreads(); xs[c] = v; __syncthreads();

    float v3 = b3[c];
    #pragma unroll 8
    for (int k = 0; k < 128; k++) v3 = fmaf(xs[k], W3[k * 128 + c], v3);

    red[c] = v3 * v3;
    __syncthreads();
    for (int off = 64; off > 0; off >>= 1) {
        if (c < off) red[c] += red[c + off];
        __syncthreads();
    }
    float nrm = fmaxf(sqrtf(red[0]), 1e-12f);
    out[g * 128 + c] = v3 / nrm;
}

// ---------------- host launch: kernel launches ONLY ----------------
extern "C" void kernel_launch(void* const* d_in, const int* in_sizes, int n_in,
                              void* d_out, int out_size) {
    const float* pos = (const float*)d_in[0];
    const int* ei = (const int*)d_in[1];
    const int* batch = (const int*)d_in[2];
    int n = in_sizes[0] / 3;
    int e = in_sizes[1] / 2;
    const int* src = ei;
    const int* dst = ei + e;
    float* out = (float*)d_out;

    const float *W[5], *bb[5], *gg[5], *be[5];
    for (int l = 0; l < 5; l++) {
        W[l]  = (const float*)d_in[3 + 4 * l];
        bb[l] = (const float*)d_in[4 + 4 * l];
        gg[l] = (const float*)d_in[5 + 4 * l];
        be[l] = (const float*)d_in[6 + 4 * l];
    }
    const float* fc0_W = (const float*)d_in[23];
    const float* fc0_b = (const float*)d_in[24];
    const float* fc1_W = (const float*)d_in[25];
    const float* fc1_b = (const float*)d_in[26];
    const float* fc2_W = (const float*)d_in[27];
    const float* fc2_b = (const float*)d_in[28];
    const float* fc3_W = (const float*)d_in[29];
    const float* fc3_b = (const float*)d_in[30];

    // ---- graph preprocessing ----
    k_zero<<<(n + 255) / 256, 256>>>(n);
    k_hist<<<(e + 255) / 256, 256>>>(dst, e);
    int nb = (n + 1023) / 1024;
    k_scan1<<<nb, 1024>>>(n);
    k_scan2<<<1, 256>>>(nb, n);
    k_place<<<(e + 255) / 256, 256>>>(src, dst, e);

    int aggBlocks = (n + 7) / 8;
    int rb128 = (n + 127) / 128;
    int rb256 = (n + 255) / 256;

    // ---- layer 1: 3 -> 16 ----
    k_agg<0><<<aggBlocks, 256>>>(pos, n, 3);
    k_gemm_s<3, 16><<<(n + 255) / 256, 256>>>(W[0], bb[0], n);
    k_finalize<<<1, 256>>>(gg[0], be[0], n, 16);

    // ---- layer 2: 16 -> 32 ----
    k_agg<1><<<aggBlocks, 256>>>(nullptr, n, 16);
    k_gemm_s<16, 32><<<(n + 255) / 256, 256>>>(W[1], bb[1], n);
    k_finalize<<<1, 256>>>(gg[1], be[1], n, 32);

    // ---- layer 3: 32 -> 64 ----
    k_agg<1><<<aggBlocks, 256>>>(nullptr, n, 32);
    k_gemm2<256, 64, 0><<<dim3(1, rb256), 256>>>(W[2], bb[2], n, 32, 64);
    k_finalize<<<1, 256>>>(gg[2], be[2], n, 64);

    // ---- layer 4: 64 -> 94 ----
    k_agg<1><<<aggBlocks, 256>>>(nullptr, n, 64);
    k_gemm2<256, 64, 0><<<dim3(2, rb256), 256>>>(W[3], bb[3], n, 64, 94);
    k_finalize<<<1, 256>>>(gg[3], be[3], n, 94);

    // ---- layer 5: 94 -> 256 ----
    k_agg<1><<<aggBlocks, 256>>>(nullptr, n, 94);
    k_gemm2<128, 128, 0><<<dim3(2, rb128), 256>>>(W[4], bb[4], n, 94, 256);
    k_finalize<<<1, 256>>>(gg[4], be[4], n, 256);

    // ---- fc0: relu(bn(g_y)) @ W (256 -> 128) + relu, into g_x ----
    k_gemm2<128, 128, 1><<<dim3(1, rb128), 256>>>(fc0_W, fc0_b, n, 256, 128);

    // ---- segment max pool + head MLP + normalize ----
    k_bounds<<<1, 65>>>(batch, n, 64);
    k_segmax<<<64, dim3(128, 4)>>>();
    k_head<<<64, 128>>>(fc1_W, fc1_b, fc2_W, fc2_b, fc3_W, fc3_b, out);
}